// round 5
// baseline (speedup 1.0000x reference)
#include <cuda_runtime.h>
#include <cuda_fp16.h>
#include <math.h>

// Problem constants (fixed dataset: N=50000, E=1.6M, avg in-degree 32)
#define MAXN 50048
#define CAP  128   // per-node adjacency capacity; Poisson(32) max over 50K nodes ~70

struct Consts {
    float Mz[4][32];   // Wz @ Lz[0:32,:]
    float Mh[4][32];   // Wh @ Lh[0:32,:]
    float cz[32];      // bz @ Lz[0:32,:] + lz
    float ch[32];      // bh @ Lh[0:32,:] + lh
    float probs[12];   // softmax(attention)
    float Wo[32][12];
    float bo[12];
};

__device__ Consts g_c;
__device__ int   g_cnt[MAXN];               // zero-init at load; k_dinv re-zeroes
__device__ int   g_deg[MAXN];
__device__ float g_dinv[MAXN];
__device__ int   g_adj[(size_t)MAXN * CAP]; // 4-byte stores (2-byte regressed: sector RMW)
__device__ uint4 g_xh[(size_t)MAXN * 6];    // x in fp16: 48 halfs = 6 x uint4 per node

// ---------------------------------------------------------------------------
// Kernel 0: compact x to fp16 rows (96B/node). Streaming, ~14 MB total.
// ---------------------------------------------------------------------------
__global__ void k_cvt(const float* __restrict__ x, int ngroups) {
    int i = blockIdx.x * blockDim.x + threadIdx.x;   // one uint4 (8 halfs) per thread
    if (i >= ngroups) return;
    float4 a = ((const float4*)x)[2 * i];
    float4 b = ((const float4*)x)[2 * i + 1];
    __half2 h0 = __floats2half2_rn(a.x, a.y);
    __half2 h1 = __floats2half2_rn(a.z, a.w);
    __half2 h2 = __floats2half2_rn(b.x, b.y);
    __half2 h3 = __floats2half2_rn(b.z, b.w);
    uint4 o;
    o.x = *reinterpret_cast<unsigned*>(&h0);
    o.y = *reinterpret_cast<unsigned*>(&h1);
    o.z = *reinterpret_cast<unsigned*>(&h2);
    o.w = *reinterpret_cast<unsigned*>(&h3);
    g_xh[i] = o;
}

// ---------------------------------------------------------------------------
// Kernel 1: single-pass bucketed adjacency build.
// ---------------------------------------------------------------------------
__global__ void k_fill(const int* __restrict__ ei, int e) {
    int t = blockIdx.x * blockDim.x + threadIdx.x;
    int i4 = t * 4;
    if (i4 >= e) return;
    if ((e & 3) == 0) {   // dataset path: e divisible by 4
        int4 r = *reinterpret_cast<const int4*>(ei + i4);       // sources
        int4 c = *reinterpret_cast<const int4*>(ei + e + i4);   // targets
        int p;
        p = atomicAdd(&g_cnt[c.x], 1); if (p < CAP) g_adj[(size_t)c.x * CAP + p] = r.x;
        p = atomicAdd(&g_cnt[c.y], 1); if (p < CAP) g_adj[(size_t)c.y * CAP + p] = r.y;
        p = atomicAdd(&g_cnt[c.z], 1); if (p < CAP) g_adj[(size_t)c.z * CAP + p] = r.z;
        p = atomicAdd(&g_cnt[c.w], 1); if (p < CAP) g_adj[(size_t)c.w * CAP + p] = r.w;
    } else {
        int end = min(i4 + 4, e);
        for (int i = i4; i < end; i++) {
            int rr = ei[i], cc = ei[e + i];
            int p = atomicAdd(&g_cnt[cc], 1);
            if (p < CAP) g_adj[(size_t)cc * CAP + p] = rr;
        }
    }
}

// ---------------------------------------------------------------------------
// Kernel 2: cnt -> (deg, dinv), re-zero cnt; block 0 also folds the weights.
// ---------------------------------------------------------------------------
__global__ void k_dinv(int n,
                       const float* __restrict__ att,
                       const float* __restrict__ Wz, const float* __restrict__ bz,
                       const float* __restrict__ Lz, const float* __restrict__ lz,
                       const float* __restrict__ Wh, const float* __restrict__ bh,
                       const float* __restrict__ Lh, const float* __restrict__ lh,
                       const float* __restrict__ Wo, const float* __restrict__ bo) {
    if (blockIdx.x == 0 && threadIdx.x < 128) {
        int tid = threadIdx.x;
        int f = tid >> 5, c = tid & 31;
        float mz = 0.f, mh = 0.f;
        #pragma unroll 8
        for (int k = 0; k < 32; k++) {
            mz = fmaf(Wz[f * 32 + k], Lz[k * 32 + c], mz);
            mh = fmaf(Wh[f * 32 + k], Lh[k * 32 + c], mh);
        }
        g_c.Mz[f][c] = mz;
        g_c.Mh[f][c] = mh;
        if (f == 0) {
            float s1 = lz[c], s2 = lh[c];
            #pragma unroll 8
            for (int k = 0; k < 32; k++) {
                s1 = fmaf(bz[k], Lz[k * 32 + c], s1);
                s2 = fmaf(bh[k], Lh[k * 32 + c], s2);
            }
            g_c.cz[c] = s1;
            g_c.ch[c] = s2;
        }
        for (int i = tid; i < 32 * 12; i += 128) ((float*)g_c.Wo)[i] = Wo[i];
        if (tid < 12) g_c.bo[tid] = bo[tid];
        if (tid == 0) {
            float m = -1e30f;
            for (int t = 0; t < 12; t++) m = fmaxf(m, att[t]);
            float ex[12]; float s = 0.f;
            for (int t = 0; t < 12; t++) { ex[t] = expf(att[t] - m); s += ex[t]; }
            float inv = 1.f / s;
            for (int t = 0; t < 12; t++) g_c.probs[t] = ex[t] * inv;
        }
    }
    int i = blockIdx.x * blockDim.x + threadIdx.x;
    if (i < n) {
        int d = g_cnt[i];
        g_cnt[i] = 0;                         // ready for next graph replay
        g_deg[i] = (d < CAP) ? d : CAP;
        g_dinv[i] = rsqrtf((float)d + 1.0f);  // +1 self loop
    }
}

// ---------------------------------------------------------------------------
// Kernel 3: warp-per-node fp16 gather. 16 slots x 2 lanes (q2 = lane&1).
// 16 edges/iter: 3 full-width LDG.128, exactly 1 sector per row per LDG
// (fp16 row = 96B = 3 sectors). f32 accumulate, butterfly reduce, GRU.
// ---------------------------------------------------------------------------
__device__ __forceinline__ void fma8(float* acc, const uint4& c, float nr) {
    const __half2* h = reinterpret_cast<const __half2*>(&c);
    #pragma unroll
    for (int w = 0; w < 4; w++) {
        float2 f = __half22float2(h[w]);
        acc[2 * w]     = fmaf(f.x, nr, acc[2 * w]);
        acc[2 * w + 1] = fmaf(f.y, nr, acc[2 * w + 1]);
    }
}

__global__ void __launch_bounds__(256) k_fused(float* __restrict__ out, int n) {
    __shared__ __align__(16) float sC[728];   // sizeof(Consts)/4
    __shared__ float shv[8][32];
    {
        const float* src = (const float*)&g_c;
        for (int i = threadIdx.x; i < 728; i += 256) sC[i] = src[i];
    }
    __syncthreads();
    const Consts* C = (const Consts*)sC;

    const unsigned FULL = 0xffffffffu;
    int warp = threadIdx.x >> 5, lane = threadIdx.x & 31;
    int node = blockIdx.x * 8 + warp;
    if (node >= n) return;

    int myslot = lane >> 1, q2 = lane & 1;
    int deg = g_deg[node];
    float dn = g_dinv[node];
    const int* adj = g_adj + (size_t)node * CAP;

    float acc[24];
    #pragma unroll
    for (int k = 0; k < 24; k++) acc[k] = 0.f;

    // self loop (norm = dn^2): slot 0 (lanes 0,1)
    if (myslot == 0) {
        const uint4* xr = g_xh + (size_t)node * 6;
        float sn = dn * dn;
        fma8(acc,      xr[q2],     sn);
        fma8(acc + 8,  xr[q2 + 2], sn);
        fma8(acc + 16, xr[q2 + 4], sn);
    }

    int iters = (deg + 15) >> 4;
    // prefetch iteration 0 (lanes 0-15)
    int s = node; float dv = 0.f;
    if (lane < 16 && lane < deg) {
        s = adj[lane];
        dv = g_dinv[s];
    }

    for (int it = 0; it < iters; it++) {
        int   cur_s = s;
        float cur_dv = dv;
        int base = (it + 1) * 16;
        if (lane < 16) {
            int idx = base + lane;
            if (idx < deg) { s = adj[idx]; dv = g_dinv[s]; }
            else           { s = node;     dv = 0.f; }
        }
        int   row = __shfl_sync(FULL, cur_s, myslot);
        float nr  = __shfl_sync(FULL, cur_dv, myslot) * dn;   // 0 for pad slots
        const uint4* xr = g_xh + (size_t)row * 6;
        uint4 c0 = xr[q2], c1 = xr[q2 + 2], c2 = xr[q2 + 4];
        fma8(acc,      c0, nr);
        fma8(acc + 8,  c1, nr);
        fma8(acc + 16, c2, nr);
    }

    // butterfly reduction over the 16 slots (lanes with equal q2)
    #pragma unroll
    for (int d = 2; d < 32; d <<= 1) {
        #pragma unroll
        for (int k = 0; k < 24; k++)
            acc[k] += __shfl_xor_sync(FULL, acc[k], d);
    }
    // every lane now holds, for its q2, chunks {q2, q2+2, q2+4} (8 floats each).

    // collapsed GRU: lane = output channel c
    float Mz0 = C->Mz[0][lane], Mz1 = C->Mz[1][lane], Mz2 = C->Mz[2][lane], Mz3 = C->Mz[3][lane];
    float Mh0 = C->Mh[0][lane], Mh1 = C->Mh[1][lane], Mh2 = C->Mh[2][lane], Mh3 = C->Mh[3][lane];
    float czc = C->cz[lane], chc = C->ch[lane];

    float H = 0.f;
    #pragma unroll
    for (int t = 0; t < 12; t++) {
        float xv[4];
        #pragma unroll
        for (int f = 0; f < 4; f++) {
            const int i = f * 12 + t;      // flat index into XA[48]
            const int c = i >> 3;          // 8-half chunk 0..5
            const int j = i & 7;
            const int srcl = c & 1;        // lane parity holding chunk c
            const int r = (c >> 1) * 8 + j;
            xv[f] = __shfl_sync(FULL, acc[r], srcl);
        }
        float pz = fmaf(xv[3], Mz3, fmaf(xv[2], Mz2, fmaf(xv[1], Mz1, fmaf(xv[0], Mz0, czc))));
        float ph = fmaf(xv[3], Mh3, fmaf(xv[2], Mh2, fmaf(xv[1], Mh1, fmaf(xv[0], Mh0, chc))));
        float Z  = 1.f / (1.f + __expf(-pz));
        float Ht = tanhf(ph);
        H = fmaf(C->probs[t] * (1.f - Z), Ht, H);
    }

    shv[warp][lane] = fmaxf(H, 0.f);
    __syncwarp();
    if (lane < 12) {
        float a = C->bo[lane];
        #pragma unroll
        for (int c2 = 0; c2 < 32; c2++)
            a = fmaf(shv[warp][c2], C->Wo[c2][lane], a);
        out[(size_t)node * 12 + lane] = a;
    }
}

// ---------------------------------------------------------------------------
extern "C" void kernel_launch(void* const* d_in, const int* in_sizes, int n_in,
                              void* d_out, int out_size) {
    const float* x   = (const float*)d_in[0];
    const int*   ei  = (const int*)  d_in[1];
    const float* att = (const float*)d_in[2];
    const float* Wz  = (const float*)d_in[3];
    const float* bz  = (const float*)d_in[4];
    const float* Lz  = (const float*)d_in[5];
    const float* lz  = (const float*)d_in[6];
    // d_in[7..10] = Wr, br, Lr, lr : provably unused (H0 == 0)
    const float* Wh  = (const float*)d_in[11];
    const float* bh  = (const float*)d_in[12];
    const float* Lh  = (const float*)d_in[13];
    const float* lh  = (const float*)d_in[14];
    const float* Wo  = (const float*)d_in[15];
    const float* bo  = (const float*)d_in[16];
    float* out = (float*)d_out;

    int n = in_sizes[0] / 48;   // [N, 4, 12]
    int e = in_sizes[1] / 2;    // [2, E]
    int ngroups = n * 6;        // 8 halfs per group

    k_cvt <<<(ngroups + 255) / 256, 256>>>(x, ngroups);
    k_fill<<<(e + 1023) / 1024, 256>>>(ei, e);
    k_dinv<<<(n + 255) / 256, 256>>>(n, att, Wz, bz, Lz, lz, Wh, bh, Lh, lh, Wo, bo);
    k_fused<<<(n + 7) / 8, 256>>>(out, n);
}

// round 6
// speedup vs baseline: 1.1473x; 1.1473x over previous
#include <cuda_runtime.h>
#include <math.h>

// Problem constants (fixed dataset: N=50000, E=1.6M, avg in-degree 32)
#define MAXN 50048
#define CAP  128   // per-node adjacency capacity; Poisson(32) max over 50K nodes ~70

struct Consts {
    float Mz[4][32];   // Wz @ Lz[0:32,:]
    float Mh[4][32];   // Wh @ Lh[0:32,:]
    float cz[32];      // bz @ Lz[0:32,:] + lz
    float ch[32];      // bh @ Lh[0:32,:] + lh
    float probs[12];   // softmax(attention)
    float Wo[32][12];
    float bo[12];
};

__device__ Consts g_c;
__device__ int   g_cnt[MAXN];               // zero-init at load; k_dinv re-zeroes
__device__ int   g_deg[MAXN];
__device__ float g_dinv[MAXN];
__device__ int   g_adj[(size_t)MAXN * CAP]; // 4-byte stores (2-byte regressed: sector RMW)

// ---------------------------------------------------------------------------
// Kernel 1: single-pass bucketed adjacency build. 8 edges/thread for MLP=8
// on the ATOMG (318 cyc) chains — kernel is latency-bound (issue was 2.7%).
// ---------------------------------------------------------------------------
__global__ void k_fill(const int* __restrict__ ei, int e) {
    int t = blockIdx.x * blockDim.x + threadIdx.x;
    int i8 = t * 8;
    if (i8 >= e) return;
    if ((e & 7) == 0) {   // dataset path: e divisible by 8
        int4 r0 = *reinterpret_cast<const int4*>(ei + i8);
        int4 r1 = *reinterpret_cast<const int4*>(ei + i8 + 4);
        int4 c0 = *reinterpret_cast<const int4*>(ei + e + i8);
        int4 c1 = *reinterpret_cast<const int4*>(ei + e + i8 + 4);
        int p0 = atomicAdd(&g_cnt[c0.x], 1);
        int p1 = atomicAdd(&g_cnt[c0.y], 1);
        int p2 = atomicAdd(&g_cnt[c0.z], 1);
        int p3 = atomicAdd(&g_cnt[c0.w], 1);
        int p4 = atomicAdd(&g_cnt[c1.x], 1);
        int p5 = atomicAdd(&g_cnt[c1.y], 1);
        int p6 = atomicAdd(&g_cnt[c1.z], 1);
        int p7 = atomicAdd(&g_cnt[c1.w], 1);
        if (p0 < CAP) g_adj[(size_t)c0.x * CAP + p0] = r0.x;
        if (p1 < CAP) g_adj[(size_t)c0.y * CAP + p1] = r0.y;
        if (p2 < CAP) g_adj[(size_t)c0.z * CAP + p2] = r0.z;
        if (p3 < CAP) g_adj[(size_t)c0.w * CAP + p3] = r0.w;
        if (p4 < CAP) g_adj[(size_t)c1.x * CAP + p4] = r1.x;
        if (p5 < CAP) g_adj[(size_t)c1.y * CAP + p5] = r1.y;
        if (p6 < CAP) g_adj[(size_t)c1.z * CAP + p6] = r1.z;
        if (p7 < CAP) g_adj[(size_t)c1.w * CAP + p7] = r1.w;
    } else {
        int end = min(i8 + 8, e);
        for (int i = i8; i < end; i++) {
            int rr = ei[i], cc = ei[e + i];
            int p = atomicAdd(&g_cnt[cc], 1);
            if (p < CAP) g_adj[(size_t)cc * CAP + p] = rr;
        }
    }
}

// ---------------------------------------------------------------------------
// Kernel 2: cnt -> (deg, dinv), re-zero cnt; block 0 also folds the weights.
// ---------------------------------------------------------------------------
__global__ void k_dinv(int n,
                       const float* __restrict__ att,
                       const float* __restrict__ Wz, const float* __restrict__ bz,
                       const float* __restrict__ Lz, const float* __restrict__ lz,
                       const float* __restrict__ Wh, const float* __restrict__ bh,
                       const float* __restrict__ Lh, const float* __restrict__ lh,
                       const float* __restrict__ Wo, const float* __restrict__ bo) {
    if (blockIdx.x == 0 && threadIdx.x < 128) {
        int tid = threadIdx.x;
        int f = tid >> 5, c = tid & 31;
        float mz = 0.f, mh = 0.f;
        #pragma unroll 8
        for (int k = 0; k < 32; k++) {
            mz = fmaf(Wz[f * 32 + k], Lz[k * 32 + c], mz);
            mh = fmaf(Wh[f * 32 + k], Lh[k * 32 + c], mh);
        }
        g_c.Mz[f][c] = mz;
        g_c.Mh[f][c] = mh;
        if (f == 0) {
            float s1 = lz[c], s2 = lh[c];
            #pragma unroll 8
            for (int k = 0; k < 32; k++) {
                s1 = fmaf(bz[k], Lz[k * 32 + c], s1);
                s2 = fmaf(bh[k], Lh[k * 32 + c], s2);
            }
            g_c.cz[c] = s1;
            g_c.ch[c] = s2;
        }
        for (int i = tid; i < 32 * 12; i += 128) ((float*)g_c.Wo)[i] = Wo[i];
        if (tid < 12) g_c.bo[tid] = bo[tid];
        if (tid == 0) {
            float m = -1e30f;
            for (int t = 0; t < 12; t++) m = fmaxf(m, att[t]);
            float ex[12]; float s = 0.f;
            for (int t = 0; t < 12; t++) { ex[t] = expf(att[t] - m); s += ex[t]; }
            float inv = 1.f / s;
            for (int t = 0; t < 12; t++) g_c.probs[t] = ex[t] * inv;
        }
    }
    int i = blockIdx.x * blockDim.x + threadIdx.x;
    if (i < n) {
        int d = g_cnt[i];
        g_cnt[i] = 0;                         // ready for next graph replay
        g_deg[i] = (d < CAP) ? d : CAP;
        g_dinv[i] = rsqrtf((float)d + 1.0f);  // +1 self loop
    }
}

// ---------------------------------------------------------------------------
// Kernel 3: warp-per-node f32 gather. Lane = (slot = lane>>2, q = lane&3).
// 8 edges/iter: each lane loads float4 chunks {q, q+4, q+8} of its slot's row.
// 12 f32 accumulators, 3-step butterfly, fast fused (1-sigmoid)*tanh GRU.
// ---------------------------------------------------------------------------
__global__ void __launch_bounds__(256) k_fused(const float* __restrict__ x,
                                               float* __restrict__ out, int n) {
    __shared__ __align__(16) float sC[728];   // sizeof(Consts)/4
    __shared__ float shv[8][32];
    {
        const float* src = (const float*)&g_c;
        for (int i = threadIdx.x; i < 728; i += 256) sC[i] = src[i];
    }
    __syncthreads();
    const Consts* C = (const Consts*)sC;

    const unsigned FULL = 0xffffffffu;
    int warp = threadIdx.x >> 5, lane = threadIdx.x & 31;
    int node = blockIdx.x * 8 + warp;
    if (node >= n) return;

    int myslot = lane >> 2, q = lane & 3;
    int deg = g_deg[node];
    float dn = g_dinv[node];
    const int* adj = g_adj + (size_t)node * CAP;

    float acc[12];
    #pragma unroll
    for (int k = 0; k < 12; k++) acc[k] = 0.f;

    // self loop (norm = dn^2): slot 0 (lanes 0-3)
    if (myslot == 0) {
        const float4* xr = (const float4*)(x + (size_t)node * 48);
        float sn = dn * dn;
        float4 v0 = xr[q], v1 = xr[q + 4], v2 = xr[q + 8];
        acc[0] = v0.x * sn; acc[1]  = v0.y * sn; acc[2]  = v0.z * sn; acc[3]  = v0.w * sn;
        acc[4] = v1.x * sn; acc[5]  = v1.y * sn; acc[6]  = v1.z * sn; acc[7]  = v1.w * sn;
        acc[8] = v2.x * sn; acc[9]  = v2.y * sn; acc[10] = v2.z * sn; acc[11] = v2.w * sn;
    }

    int iters = (deg + 7) >> 3;
    // prefetch iteration 0 (lanes 0-7)
    int s = node; float dv = 0.f;
    if (lane < 8 && lane < deg) {
        s = adj[lane];
        dv = g_dinv[s];
    }

    for (int it = 0; it < iters; it++) {
        int   cur_s = s;
        float cur_dv = dv;
        int base = (it + 1) * 8;
        if (lane < 8) {
            int idx = base + lane;
            if (idx < deg) { s = adj[idx]; dv = g_dinv[s]; }
            else           { s = node;     dv = 0.f; }
        }
        int   row = __shfl_sync(FULL, cur_s, myslot);
        float nr  = __shfl_sync(FULL, cur_dv, myslot) * dn;   // 0 for pad slots
        const float4* xr = (const float4*)(x + (size_t)row * 48);
        float4 v0 = xr[q], v1 = xr[q + 4], v2 = xr[q + 8];
        acc[0]  = fmaf(v0.x, nr, acc[0]);  acc[1]  = fmaf(v0.y, nr, acc[1]);
        acc[2]  = fmaf(v0.z, nr, acc[2]);  acc[3]  = fmaf(v0.w, nr, acc[3]);
        acc[4]  = fmaf(v1.x, nr, acc[4]);  acc[5]  = fmaf(v1.y, nr, acc[5]);
        acc[6]  = fmaf(v1.z, nr, acc[6]);  acc[7]  = fmaf(v1.w, nr, acc[7]);
        acc[8]  = fmaf(v2.x, nr, acc[8]);  acc[9]  = fmaf(v2.y, nr, acc[9]);
        acc[10] = fmaf(v2.z, nr, acc[10]); acc[11] = fmaf(v2.w, nr, acc[11]);
    }

    // butterfly reduction over the 8 slots (lanes with equal q)
    #pragma unroll
    for (int d = 4; d < 32; d <<= 1) {
        #pragma unroll
        for (int k = 0; k < 12; k++)
            acc[k] += __shfl_xor_sync(FULL, acc[k], d);
    }
    // every lane now holds, for its q: chunk q in acc[0..3], q+4 in acc[4..7],
    // q+8 in acc[8..11].

    // collapsed GRU: lane = output channel c
    float Mz0 = C->Mz[0][lane], Mz1 = C->Mz[1][lane], Mz2 = C->Mz[2][lane], Mz3 = C->Mz[3][lane];
    float Mh0 = C->Mh[0][lane], Mh1 = C->Mh[1][lane], Mh2 = C->Mh[2][lane], Mh3 = C->Mh[3][lane];
    float czc = C->cz[lane], chc = C->ch[lane];

    float H = 0.f;
    #pragma unroll
    for (int t = 0; t < 12; t++) {
        float xv[4];
        #pragma unroll
        for (int f = 0; f < 4; f++) {
            const int i = f * 12 + t;      // flat index into XA[48]
            const int c = i >> 2;          // float4 chunk 0..11
            const int r = (c >> 2) * 4 + (i & 3);   // register within acc[12]
            xv[f] = __shfl_sync(FULL, acc[r], c & 3);
        }
        float pz = fmaf(xv[3], Mz3, fmaf(xv[2], Mz2, fmaf(xv[1], Mz1, fmaf(xv[0], Mz0, czc))));
        float ph = fmaf(xv[3], Mh3, fmaf(xv[2], Mh2, fmaf(xv[1], Mh1, fmaf(xv[0], Mh0, chc))));
        // (1 - sigmoid(pz)) * tanh(ph) = (b-1) / ((1+a)(b+1)),
        // a = e^pz, b = e^{2 ph} (capped: limits stay exact, no inf*0 NaN)
        float a = __expf(pz);
        float b = fminf(__expf(2.0f * ph), 1e30f);
        float val = __fdividef(b - 1.0f, (1.0f + a) * (b + 1.0f));
        H = fmaf(val, C->probs[t], H);
    }

    shv[warp][lane] = fmaxf(H, 0.f);
    __syncwarp();
    if (lane < 12) {
        float acc_o = C->bo[lane];
        #pragma unroll
        for (int c2 = 0; c2 < 32; c2++)
            acc_o = fmaf(shv[warp][c2], C->Wo[c2][lane], acc_o);
        out[(size_t)node * 12 + lane] = acc_o;
    }
}

// ---------------------------------------------------------------------------
extern "C" void kernel_launch(void* const* d_in, const int* in_sizes, int n_in,
                              void* d_out, int out_size) {
    const float* x   = (const float*)d_in[0];
    const int*   ei  = (const int*)  d_in[1];
    const float* att = (const float*)d_in[2];
    const float* Wz  = (const float*)d_in[3];
    const float* bz  = (const float*)d_in[4];
    const float* Lz  = (const float*)d_in[5];
    const float* lz  = (const float*)d_in[6];
    // d_in[7..10] = Wr, br, Lr, lr : provably unused (H0 == 0)
    const float* Wh  = (const float*)d_in[11];
    const float* bh  = (const float*)d_in[12];
    const float* Lh  = (const float*)d_in[13];
    const float* lh  = (const float*)d_in[14];
    const float* Wo  = (const float*)d_in[15];
    const float* bo  = (const float*)d_in[16];
    float* out = (float*)d_out;

    int n = in_sizes[0] / 48;   // [N, 4, 12]
    int e = in_sizes[1] / 2;    // [2, E]

    k_fill<<<(e + 2047) / 2048, 256>>>(ei, e);
    k_dinv<<<(n + 255) / 256, 256>>>(n, att, Wz, bz, Lz, lz, Wh, bh, Lh, lh, Wo, bo);
    k_fused<<<(n + 7) / 8, 256>>>(x, out, n);
}

// round 7
// speedup vs baseline: 1.2230x; 1.0659x over previous
#include <cuda_runtime.h>
#include <math.h>

// Problem constants (fixed dataset: N=50000, E=1.6M, avg in-degree 32)
#define MAXN 50048
#define CAP  128   // per-node adjacency capacity; Poisson(32) max over 50K nodes ~70

struct Consts {
    float Mz[4][32];   // Wz @ Lz[0:32,:]
    float Mh[4][32];   // Wh @ Lh[0:32,:]
    float cz[32];      // bz @ Lz[0:32,:] + lz
    float ch[32];      // bh @ Lh[0:32,:] + lh
    float probs[12];   // 0.5 * softmax(attention)  (0.5 folded from GRU identity)
    float Wo[32][12];
    float bo[12];
};

__device__ Consts g_c;
__device__ int   g_cnt[MAXN];               // zero-init at load; k_dinv re-zeroes
__device__ int   g_deg[MAXN];
__device__ float g_dinv[MAXN];
__device__ int   g_adj[(size_t)MAXN * CAP]; // 4-byte stores (2-byte regressed: sector RMW)

// ---------------------------------------------------------------------------
// Kernel 1: single-pass bucketed adjacency build. 4 edges/thread (best R2 cfg:
// grid 1563 -> 10.6 blocks/SM, occ ~88%; 8/thread starved the grid).
// ---------------------------------------------------------------------------
__global__ void k_fill(const int* __restrict__ ei, int e) {
    int t = blockIdx.x * blockDim.x + threadIdx.x;
    int i4 = t * 4;
    if (i4 >= e) return;
    if ((e & 3) == 0) {   // dataset path: e divisible by 4
        int4 r = *reinterpret_cast<const int4*>(ei + i4);       // sources
        int4 c = *reinterpret_cast<const int4*>(ei + e + i4);   // targets
        int p0 = atomicAdd(&g_cnt[c.x], 1);
        int p1 = atomicAdd(&g_cnt[c.y], 1);
        int p2 = atomicAdd(&g_cnt[c.z], 1);
        int p3 = atomicAdd(&g_cnt[c.w], 1);
        if (p0 < CAP) g_adj[(size_t)c.x * CAP + p0] = r.x;
        if (p1 < CAP) g_adj[(size_t)c.y * CAP + p1] = r.y;
        if (p2 < CAP) g_adj[(size_t)c.z * CAP + p2] = r.z;
        if (p3 < CAP) g_adj[(size_t)c.w * CAP + p3] = r.w;
    } else {
        int end = min(i4 + 4, e);
        for (int i = i4; i < end; i++) {
            int rr = ei[i], cc = ei[e + i];
            int p = atomicAdd(&g_cnt[cc], 1);
            if (p < CAP) g_adj[(size_t)cc * CAP + p] = rr;
        }
    }
}

// ---------------------------------------------------------------------------
// Kernel 2: cnt -> (deg, dinv), re-zero cnt; block 0 also folds the weights.
// ---------------------------------------------------------------------------
__global__ void k_dinv(int n,
                       const float* __restrict__ att,
                       const float* __restrict__ Wz, const float* __restrict__ bz,
                       const float* __restrict__ Lz, const float* __restrict__ lz,
                       const float* __restrict__ Wh, const float* __restrict__ bh,
                       const float* __restrict__ Lh, const float* __restrict__ lh,
                       const float* __restrict__ Wo, const float* __restrict__ bo) {
    if (blockIdx.x == 0 && threadIdx.x < 128) {
        int tid = threadIdx.x;
        int f = tid >> 5, c = tid & 31;
        float mz = 0.f, mh = 0.f;
        #pragma unroll 8
        for (int k = 0; k < 32; k++) {
            mz = fmaf(Wz[f * 32 + k], Lz[k * 32 + c], mz);
            mh = fmaf(Wh[f * 32 + k], Lh[k * 32 + c], mh);
        }
        g_c.Mz[f][c] = mz;
        g_c.Mh[f][c] = mh;
        if (f == 0) {
            float s1 = lz[c], s2 = lh[c];
            #pragma unroll 8
            for (int k = 0; k < 32; k++) {
                s1 = fmaf(bz[k], Lz[k * 32 + c], s1);
                s2 = fmaf(bh[k], Lh[k * 32 + c], s2);
            }
            g_c.cz[c] = s1;
            g_c.ch[c] = s2;
        }
        for (int i = tid; i < 32 * 12; i += 128) ((float*)g_c.Wo)[i] = Wo[i];
        if (tid < 12) g_c.bo[tid] = bo[tid];
        if (tid == 0) {
            float m = -1e30f;
            for (int t = 0; t < 12; t++) m = fmaxf(m, att[t]);
            float ex[12]; float s = 0.f;
            for (int t = 0; t < 12; t++) { ex[t] = expf(att[t] - m); s += ex[t]; }
            float inv = 0.5f / s;   // 0.5 from (1-sigmoid)*tanh identity folded here
            for (int t = 0; t < 12; t++) g_c.probs[t] = ex[t] * inv;
        }
    }
    int i = blockIdx.x * blockDim.x + threadIdx.x;
    if (i < n) {
        int d = g_cnt[i];
        g_cnt[i] = 0;                         // ready for next graph replay
        g_deg[i] = (d < CAP) ? d : CAP;
        g_dinv[i] = rsqrtf((float)d + 1.0f);  // +1 self loop
    }
}

// ---------------------------------------------------------------------------
// Kernel 3: warp-per-node f32 gather. Lane = (slot = lane>>2, q = lane&3).
// 8 edges/iter: each lane loads float4 chunks {q, q+4, q+8} of its slot's row.
// 12 f32 accumulators, 3-step butterfly, MUFU.TANH GRU epilogue.
// launch_bounds(256,5): cap regs ~51 -> 5 blocks/SM (occ 45% -> ~62%).
// ---------------------------------------------------------------------------
__device__ __forceinline__ float fast_tanh(float v) {
    float r;
    asm("tanh.approx.f32 %0, %1;" : "=f"(r) : "f"(v));
    return r;
}

__global__ void __launch_bounds__(256, 5) k_fused(const float* __restrict__ x,
                                                  float* __restrict__ out, int n) {
    __shared__ __align__(16) float sC[728];   // sizeof(Consts)/4
    __shared__ float shv[8][32];
    {
        const float* src = (const float*)&g_c;
        for (int i = threadIdx.x; i < 728; i += 256) sC[i] = src[i];
    }
    __syncthreads();
    const Consts* C = (const Consts*)sC;

    const unsigned FULL = 0xffffffffu;
    int warp = threadIdx.x >> 5, lane = threadIdx.x & 31;
    int node = blockIdx.x * 8 + warp;
    if (node >= n) return;

    int myslot = lane >> 2, q = lane & 3;
    int deg = g_deg[node];
    float dn = g_dinv[node];
    const int* adj = g_adj + (size_t)node * CAP;

    float acc[12];
    #pragma unroll
    for (int k = 0; k < 12; k++) acc[k] = 0.f;

    // self loop (norm = dn^2): slot 0 (lanes 0-3)
    if (myslot == 0) {
        const float4* xr = (const float4*)(x + (size_t)node * 48);
        float sn = dn * dn;
        float4 v0 = xr[q], v1 = xr[q + 4], v2 = xr[q + 8];
        acc[0] = v0.x * sn; acc[1]  = v0.y * sn; acc[2]  = v0.z * sn; acc[3]  = v0.w * sn;
        acc[4] = v1.x * sn; acc[5]  = v1.y * sn; acc[6]  = v1.z * sn; acc[7]  = v1.w * sn;
        acc[8] = v2.x * sn; acc[9]  = v2.y * sn; acc[10] = v2.z * sn; acc[11] = v2.w * sn;
    }

    int iters = (deg + 7) >> 3;
    // prefetch iteration 0 (lanes 0-7)
    int s = node; float dv = 0.f;
    if (lane < 8 && lane < deg) {
        s = adj[lane];
        dv = g_dinv[s];
    }

    for (int it = 0; it < iters; it++) {
        int   cur_s = s;
        float cur_dv = dv;
        int base = (it + 1) * 8;
        if (lane < 8) {
            int idx = base + lane;
            if (idx < deg) { s = adj[idx]; dv = g_dinv[s]; }
            else           { s = node;     dv = 0.f; }
        }
        int   row = __shfl_sync(FULL, cur_s, myslot);
        float nr  = __shfl_sync(FULL, cur_dv, myslot) * dn;   // 0 for pad slots
        const float4* xr = (const float4*)(x + (size_t)row * 48);
        float4 v0 = xr[q], v1 = xr[q + 4], v2 = xr[q + 8];
        acc[0]  = fmaf(v0.x, nr, acc[0]);  acc[1]  = fmaf(v0.y, nr, acc[1]);
        acc[2]  = fmaf(v0.z, nr, acc[2]);  acc[3]  = fmaf(v0.w, nr, acc[3]);
        acc[4]  = fmaf(v1.x, nr, acc[4]);  acc[5]  = fmaf(v1.y, nr, acc[5]);
        acc[6]  = fmaf(v1.z, nr, acc[6]);  acc[7]  = fmaf(v1.w, nr, acc[7]);
        acc[8]  = fmaf(v2.x, nr, acc[8]);  acc[9]  = fmaf(v2.y, nr, acc[9]);
        acc[10] = fmaf(v2.z, nr, acc[10]); acc[11] = fmaf(v2.w, nr, acc[11]);
    }

    // butterfly reduction over the 8 slots (lanes with equal q)
    #pragma unroll
    for (int d = 4; d < 32; d <<= 1) {
        #pragma unroll
        for (int k = 0; k < 12; k++)
            acc[k] += __shfl_xor_sync(FULL, acc[k], d);
    }
    // every lane now holds, for its q: chunk q in acc[0..3], q+4 in acc[4..7],
    // q+8 in acc[8..11].

    // collapsed GRU: lane = output channel c
    float Mz0 = C->Mz[0][lane], Mz1 = C->Mz[1][lane], Mz2 = C->Mz[2][lane], Mz3 = C->Mz[3][lane];
    float Mh0 = C->Mh[0][lane], Mh1 = C->Mh[1][lane], Mh2 = C->Mh[2][lane], Mh3 = C->Mh[3][lane];
    float czc = C->cz[lane], chc = C->ch[lane];

    float H = 0.f;
    #pragma unroll
    for (int t = 0; t < 12; t++) {
        float xv[4];
        #pragma unroll
        for (int f = 0; f < 4; f++) {
            const int i = f * 12 + t;      // flat index into XA[48]
            const int c = i >> 2;          // float4 chunk 0..11
            const int r = (c >> 2) * 4 + (i & 3);   // register within acc[12]
            xv[f] = __shfl_sync(FULL, acc[r], c & 3);
        }
        float pz = fmaf(xv[3], Mz3, fmaf(xv[2], Mz2, fmaf(xv[1], Mz1, fmaf(xv[0], Mz0, czc))));
        float ph = fmaf(xv[3], Mh3, fmaf(xv[2], Mh2, fmaf(xv[1], Mh1, fmaf(xv[0], Mh0, chc))));
        // (1 - sigmoid(pz)) * tanh(ph) = 0.5 * (1 - tanh(pz/2)) * tanh(ph);
        // 0.5 folded into C->probs. MUFU.TANH: 2 MUFU vs 3 (exp/exp/rcp).
        float tA = fast_tanh(0.5f * pz);
        float tB = fast_tanh(ph);
        float val = (1.0f - tA) * tB;
        H = fmaf(val, C->probs[t], H);
    }

    shv[warp][lane] = fmaxf(H, 0.f);
    __syncwarp();
    if (lane < 12) {
        float acc_o = C->bo[lane];
        #pragma unroll
        for (int c2 = 0; c2 < 32; c2++)
            acc_o = fmaf(shv[warp][c2], C->Wo[c2][lane], acc_o);
        out[(size_t)node * 12 + lane] = acc_o;
    }
}

// ---------------------------------------------------------------------------
extern "C" void kernel_launch(void* const* d_in, const int* in_sizes, int n_in,
                              void* d_out, int out_size) {
    const float* x   = (const float*)d_in[0];
    const int*   ei  = (const int*)  d_in[1];
    const float* att = (const float*)d_in[2];
    const float* Wz  = (const float*)d_in[3];
    const float* bz  = (const float*)d_in[4];
    const float* Lz  = (const float*)d_in[5];
    const float* lz  = (const float*)d_in[6];
    // d_in[7..10] = Wr, br, Lr, lr : provably unused (H0 == 0)
    const float* Wh  = (const float*)d_in[11];
    const float* bh  = (const float*)d_in[12];
    const float* Lh  = (const float*)d_in[13];
    const float* lh  = (const float*)d_in[14];
    const float* Wo  = (const float*)d_in[15];
    const float* bo  = (const float*)d_in[16];
    float* out = (float*)d_out;

    int n = in_sizes[0] / 48;   // [N, 4, 12]
    int e = in_sizes[1] / 2;    // [2, E]

    k_fill<<<(e + 1023) / 1024, 256>>>(ei, e);
    k_dinv<<<(n + 255) / 256, 256>>>(n, att, Wz, bz, Lz, lz, Wh, bh, Lh, lh, Wo, bo);
    k_fused<<<(n + 7) / 8, 256>>>(x, out, n);
}

// round 8
// speedup vs baseline: 1.2270x; 1.0033x over previous
#include <cuda_runtime.h>
#include <cuda_fp16.h>
#include <math.h>

// Problem constants (fixed dataset: N=50000, E=1.6M, avg in-degree 32)
#define MAXN 50048
#define CAP  128   // per-node adjacency capacity; Poisson(32) max over 50K nodes ~70

struct Consts {
    float Mz[4][32];   // Wz @ Lz[0:32,:]
    float Mh[4][32];   // Wh @ Lh[0:32,:]
    float cz[32];      // bz @ Lz[0:32,:] + lz
    float ch[32];      // bh @ Lh[0:32,:] + lh
    float probs[12];   // 0.5 * softmax(attention)  (0.5 folded from GRU identity)
    float Wo[32][12];
    float bo[12];
};

__device__ Consts g_c;
__device__ int   g_cnt[MAXN];               // zero-init at load; k_dinv re-zeroes
__device__ int   g_deg[MAXN];
__device__ float g_dinv[MAXN];
__device__ int   g_adj[(size_t)MAXN * CAP]; // 4-byte stores (2-byte regressed: sector RMW)
__device__ uint2 g_xh[(size_t)MAXN * 12];   // x in fp16: 48 halfs = 12 x uint2 per node

// ---------------------------------------------------------------------------
// Kernel 0: compact x to fp16 rows (96B/node). Streaming ~14 MB.
// g_xh[node*12 + j] holds x-halfs [4j .. 4j+3] of that node's 48-value row.
// ---------------------------------------------------------------------------
__global__ void k_cvt(const float* __restrict__ x, int nchunks) {
    int i = blockIdx.x * blockDim.x + threadIdx.x;   // one uint2 (4 halfs) per thread
    if (i >= nchunks) return;
    float4 a = ((const float4*)x)[i];
    __half2 h0 = __floats2half2_rn(a.x, a.y);
    __half2 h1 = __floats2half2_rn(a.z, a.w);
    uint2 o;
    o.x = *reinterpret_cast<unsigned*>(&h0);
    o.y = *reinterpret_cast<unsigned*>(&h1);
    g_xh[i] = o;
}

// ---------------------------------------------------------------------------
// Kernel 1: single-pass bucketed adjacency build (best cfg: 4 edges/thread).
// ---------------------------------------------------------------------------
__global__ void k_fill(const int* __restrict__ ei, int e) {
    int t = blockIdx.x * blockDim.x + threadIdx.x;
    int i4 = t * 4;
    if (i4 >= e) return;
    if ((e & 3) == 0) {   // dataset path: e divisible by 4
        int4 r = *reinterpret_cast<const int4*>(ei + i4);       // sources
        int4 c = *reinterpret_cast<const int4*>(ei + e + i4);   // targets
        int p0 = atomicAdd(&g_cnt[c.x], 1);
        int p1 = atomicAdd(&g_cnt[c.y], 1);
        int p2 = atomicAdd(&g_cnt[c.z], 1);
        int p3 = atomicAdd(&g_cnt[c.w], 1);
        if (p0 < CAP) g_adj[(size_t)c.x * CAP + p0] = r.x;
        if (p1 < CAP) g_adj[(size_t)c.y * CAP + p1] = r.y;
        if (p2 < CAP) g_adj[(size_t)c.z * CAP + p2] = r.z;
        if (p3 < CAP) g_adj[(size_t)c.w * CAP + p3] = r.w;
    } else {
        int end = min(i4 + 4, e);
        for (int i = i4; i < end; i++) {
            int rr = ei[i], cc = ei[e + i];
            int p = atomicAdd(&g_cnt[cc], 1);
            if (p < CAP) g_adj[(size_t)cc * CAP + p] = rr;
        }
    }
}

// ---------------------------------------------------------------------------
// Kernel 2: cnt -> (deg, dinv), re-zero cnt; block 0 also folds the weights.
// ---------------------------------------------------------------------------
__global__ void k_dinv(int n,
                       const float* __restrict__ att,
                       const float* __restrict__ Wz, const float* __restrict__ bz,
                       const float* __restrict__ Lz, const float* __restrict__ lz,
                       const float* __restrict__ Wh, const float* __restrict__ bh,
                       const float* __restrict__ Lh, const float* __restrict__ lh,
                       const float* __restrict__ Wo, const float* __restrict__ bo) {
    if (blockIdx.x == 0 && threadIdx.x < 128) {
        int tid = threadIdx.x;
        int f = tid >> 5, c = tid & 31;
        float mz = 0.f, mh = 0.f;
        #pragma unroll 8
        for (int k = 0; k < 32; k++) {
            mz = fmaf(Wz[f * 32 + k], Lz[k * 32 + c], mz);
            mh = fmaf(Wh[f * 32 + k], Lh[k * 32 + c], mh);
        }
        g_c.Mz[f][c] = mz;
        g_c.Mh[f][c] = mh;
        if (f == 0) {
            float s1 = lz[c], s2 = lh[c];
            #pragma unroll 8
            for (int k = 0; k < 32; k++) {
                s1 = fmaf(bz[k], Lz[k * 32 + c], s1);
                s2 = fmaf(bh[k], Lh[k * 32 + c], s2);
            }
            g_c.cz[c] = s1;
            g_c.ch[c] = s2;
        }
        for (int i = tid; i < 32 * 12; i += 128) ((float*)g_c.Wo)[i] = Wo[i];
        if (tid < 12) g_c.bo[tid] = bo[tid];
        if (tid == 0) {
            float m = -1e30f;
            for (int t = 0; t < 12; t++) m = fmaxf(m, att[t]);
            float ex[12]; float s = 0.f;
            for (int t = 0; t < 12; t++) { ex[t] = expf(att[t] - m); s += ex[t]; }
            float inv = 0.5f / s;   // 0.5 from (1-sigmoid)*tanh identity folded here
            for (int t = 0; t < 12; t++) g_c.probs[t] = ex[t] * inv;
        }
    }
    int i = blockIdx.x * blockDim.x + threadIdx.x;
    if (i < n) {
        int d = g_cnt[i];
        g_cnt[i] = 0;                         // ready for next graph replay
        g_deg[i] = (d < CAP) ? d : CAP;
        g_dinv[i] = rsqrtf((float)d + 1.0f);  // +1 self loop
    }
}

// ---------------------------------------------------------------------------
// Kernel 3: warp-per-node fp16 gather via uint2 (8B) loads.
// Lane = (slot = lane>>2, q = lane&3). 8 edges/iter, 4 lanes/row; each lane
// loads uint2 chunks {q, q+4, q+8} of its slot's fp16 row (96B = 3 sectors).
// 12 f32 accumulators, 3-step butterfly, MUFU.TANH GRU epilogue.
// ---------------------------------------------------------------------------
__device__ __forceinline__ float fast_tanh(float v) {
    float r;
    asm("tanh.approx.f32 %0, %1;" : "=f"(r) : "f"(v));
    return r;
}

__device__ __forceinline__ void fma4(float* acc, const uint2& c, float nr) {
    __half2 h0 = *reinterpret_cast<const __half2*>(&c.x);
    __half2 h1 = *reinterpret_cast<const __half2*>(&c.y);
    float2 f0 = __half22float2(h0);
    float2 f1 = __half22float2(h1);
    acc[0] = fmaf(f0.x, nr, acc[0]);
    acc[1] = fmaf(f0.y, nr, acc[1]);
    acc[2] = fmaf(f1.x, nr, acc[2]);
    acc[3] = fmaf(f1.y, nr, acc[3]);
}

__global__ void __launch_bounds__(256, 5) k_fused(float* __restrict__ out, int n) {
    __shared__ __align__(16) float sC[728];   // sizeof(Consts)/4
    __shared__ float shv[8][32];
    {
        const float* src = (const float*)&g_c;
        for (int i = threadIdx.x; i < 728; i += 256) sC[i] = src[i];
    }
    __syncthreads();
    const Consts* C = (const Consts*)sC;

    const unsigned FULL = 0xffffffffu;
    int warp = threadIdx.x >> 5, lane = threadIdx.x & 31;
    int node = blockIdx.x * 8 + warp;
    if (node >= n) return;

    int myslot = lane >> 2, q = lane & 3;
    int deg = g_deg[node];
    float dn = g_dinv[node];
    const int* adj = g_adj + (size_t)node * CAP;

    float acc[12];
    #pragma unroll
    for (int k = 0; k < 12; k++) acc[k] = 0.f;

    // self loop (norm = dn^2): slot 0 (lanes 0-3)
    if (myslot == 0) {
        const uint2* xr = g_xh + (size_t)node * 12;
        float sn = dn * dn;
        fma4(acc,     xr[q],     sn);
        fma4(acc + 4, xr[q + 4], sn);
        fma4(acc + 8, xr[q + 8], sn);
    }

    int iters = (deg + 7) >> 3;
    // prefetch iteration 0 (lanes 0-7)
    int s = node; float dv = 0.f;
    if (lane < 8 && lane < deg) {
        s = adj[lane];
        dv = g_dinv[s];
    }

    for (int it = 0; it < iters; it++) {
        int   cur_s = s;
        float cur_dv = dv;
        int base = (it + 1) * 8;
        if (lane < 8) {
            int idx = base + lane;
            if (idx < deg) { s = adj[idx]; dv = g_dinv[s]; }
            else           { s = node;     dv = 0.f; }
        }
        int   row = __shfl_sync(FULL, cur_s, myslot);
        float nr  = __shfl_sync(FULL, cur_dv, myslot) * dn;   // 0 for pad slots
        const uint2* xr = g_xh + (size_t)row * 12;
        uint2 c0 = xr[q], c1 = xr[q + 4], c2 = xr[q + 8];
        fma4(acc,     c0, nr);
        fma4(acc + 4, c1, nr);
        fma4(acc + 8, c2, nr);
    }

    // butterfly reduction over the 8 slots (lanes with equal q)
    #pragma unroll
    for (int d = 4; d < 32; d <<= 1) {
        #pragma unroll
        for (int k = 0; k < 12; k++)
            acc[k] += __shfl_xor_sync(FULL, acc[k], d);
    }
    // every lane holds, for its q: 4-value chunk q in acc[0..3], q+4 in
    // acc[4..7], q+8 in acc[8..11]  (same mapping as the f32 float4 version).

    // collapsed GRU: lane = output channel c
    float Mz0 = C->Mz[0][lane], Mz1 = C->Mz[1][lane], Mz2 = C->Mz[2][lane], Mz3 = C->Mz[3][lane];
    float Mh0 = C->Mh[0][lane], Mh1 = C->Mh[1][lane], Mh2 = C->Mh[2][lane], Mh3 = C->Mh[3][lane];
    float czc = C->cz[lane], chc = C->ch[lane];

    float H = 0.f;
    #pragma unroll
    for (int t = 0; t < 12; t++) {
        float xv[4];
        #pragma unroll
        for (int f = 0; f < 4; f++) {
            const int i = f * 12 + t;      // flat index into XA[48]
            const int c = i >> 2;          // 4-value chunk 0..11
            const int r = (c >> 2) * 4 + (i & 3);   // register within acc[12]
            xv[f] = __shfl_sync(FULL, acc[r], c & 3);
        }
        float pz = fmaf(xv[3], Mz3, fmaf(xv[2], Mz2, fmaf(xv[1], Mz1, fmaf(xv[0], Mz0, czc))));
        float ph = fmaf(xv[3], Mh3, fmaf(xv[2], Mh2, fmaf(xv[1], Mh1, fmaf(xv[0], Mh0, chc))));
        // (1 - sigmoid(pz)) * tanh(ph) = 0.5 * (1 - tanh(pz/2)) * tanh(ph);
        // the 0.5 is folded into C->probs.
        float tA = fast_tanh(0.5f * pz);
        float tB = fast_tanh(ph);
        float val = (1.0f - tA) * tB;
        H = fmaf(val, C->probs[t], H);
    }

    shv[warp][lane] = fmaxf(H, 0.f);
    __syncwarp();
    if (lane < 12) {
        float acc_o = C->bo[lane];
        #pragma unroll
        for (int c2 = 0; c2 < 32; c2++)
            acc_o = fmaf(shv[warp][c2], C->Wo[c2][lane], acc_o);
        out[(size_t)node * 12 + lane] = acc_o;
    }
}

// ---------------------------------------------------------------------------
extern "C" void kernel_launch(void* const* d_in, const int* in_sizes, int n_in,
                              void* d_out, int out_size) {
    const float* x   = (const float*)d_in[0];
    const int*   ei  = (const int*)  d_in[1];
    const float* att = (const float*)d_in[2];
    const float* Wz  = (const float*)d_in[3];
    const float* bz  = (const float*)d_in[4];
    const float* Lz  = (const float*)d_in[5];
    const float* lz  = (const float*)d_in[6];
    // d_in[7..10] = Wr, br, Lr, lr : provably unused (H0 == 0)
    const float* Wh  = (const float*)d_in[11];
    const float* bh  = (const float*)d_in[12];
    const float* Lh  = (const float*)d_in[13];
    const float* lh  = (const float*)d_in[14];
    const float* Wo  = (const float*)d_in[15];
    const float* bo  = (const float*)d_in[16];
    float* out = (float*)d_out;

    int n = in_sizes[0] / 48;   // [N, 4, 12]
    int e = in_sizes[1] / 2;    // [2, E]
    int nchunks = n * 12;       // 4 halfs per chunk

    k_cvt <<<(nchunks + 255) / 256, 256>>>(x, nchunks);
    k_fill<<<(e + 1023) / 1024, 256>>>(ei, e);
    k_dinv<<<(n + 255) / 256, 256>>>(n, att, Wz, bz, Lz, lz, Wh, bh, Lh, lh, Wo, bo);
    k_fused<<<(n + 7) / 8, 256>>>(out, n);
}

// round 9
// speedup vs baseline: 1.3220x; 1.0775x over previous
#include <cuda_runtime.h>
#include <cuda_fp16.h>
#include <math.h>

// Problem constants (fixed dataset: N=50000, E=1.6M, avg in-degree 32)
#define MAXN 50048
#define CAP  128   // per-node adjacency capacity; Poisson(32) max over 50K nodes ~70

struct Consts {
    float Mz[4][32];   // Wz @ Lz[0:32,:]
    float Mh[4][32];   // Wh @ Lh[0:32,:]
    float cz[32];      // bz @ Lz[0:32,:] + lz
    float ch[32];      // bh @ Lh[0:32,:] + lh
    float probs[12];   // 0.5 * softmax(attention)  (0.5 folded from GRU identity)
    float Wo[32][12];
    float bo[12];
};

__device__ Consts g_c;
__device__ int   g_cnt[MAXN];               // zero-init at load; k_dinv re-zeroes
__device__ int   g_deg[MAXN];
__device__ float g_dinv[MAXN];
__device__ int   g_adj[(size_t)MAXN * CAP];
// x in fp16, one node row = 48 halfs padded to 128 B = 8 x uint4 (chunks 6,7 zero).
// 128B-aligned rows: each gathered row is exactly ONE L1 cache line.
__device__ __align__(128) uint4 g_xh[(size_t)MAXN * 8];

// ---------------------------------------------------------------------------
// Kernel 0: compact x to padded fp16 rows (128B/node, data in first 96B).
// ---------------------------------------------------------------------------
__global__ void k_cvt(const float* __restrict__ x, int nchunks) {
    int i = blockIdx.x * blockDim.x + threadIdx.x;   // one uint4 (8 halfs) out
    if (i >= nchunks) return;
    int node = i >> 3, h = i & 7;
    uint4 o = make_uint4(0u, 0u, 0u, 0u);
    if (h < 6) {
        const float4* src = (const float4*)(x + (size_t)node * 48 + h * 8);
        float4 a = src[0];
        float4 b = src[1];
        __half2 h0 = __floats2half2_rn(a.x, a.y);
        __half2 h1 = __floats2half2_rn(a.z, a.w);
        __half2 h2 = __floats2half2_rn(b.x, b.y);
        __half2 h3 = __floats2half2_rn(b.z, b.w);
        o.x = *reinterpret_cast<unsigned*>(&h0);
        o.y = *reinterpret_cast<unsigned*>(&h1);
        o.z = *reinterpret_cast<unsigned*>(&h2);
        o.w = *reinterpret_cast<unsigned*>(&h3);
    }
    g_xh[i] = o;
}

// ---------------------------------------------------------------------------
// Kernel 1: single-pass bucketed adjacency build (best cfg: 4 edges/thread).
// ---------------------------------------------------------------------------
__global__ void k_fill(const int* __restrict__ ei, int e) {
    int t = blockIdx.x * blockDim.x + threadIdx.x;
    int i4 = t * 4;
    if (i4 >= e) return;
    if ((e & 3) == 0) {   // dataset path: e divisible by 4
        int4 r = *reinterpret_cast<const int4*>(ei + i4);       // sources
        int4 c = *reinterpret_cast<const int4*>(ei + e + i4);   // targets
        int p0 = atomicAdd(&g_cnt[c.x], 1);
        int p1 = atomicAdd(&g_cnt[c.y], 1);
        int p2 = atomicAdd(&g_cnt[c.z], 1);
        int p3 = atomicAdd(&g_cnt[c.w], 1);
        if (p0 < CAP) g_adj[(size_t)c.x * CAP + p0] = r.x;
        if (p1 < CAP) g_adj[(size_t)c.y * CAP + p1] = r.y;
        if (p2 < CAP) g_adj[(size_t)c.z * CAP + p2] = r.z;
        if (p3 < CAP) g_adj[(size_t)c.w * CAP + p3] = r.w;
    } else {
        int end = min(i4 + 4, e);
        for (int i = i4; i < end; i++) {
            int rr = ei[i], cc = ei[e + i];
            int p = atomicAdd(&g_cnt[cc], 1);
            if (p < CAP) g_adj[(size_t)cc * CAP + p] = rr;
        }
    }
}

// ---------------------------------------------------------------------------
// Kernel 2: cnt -> (deg, dinv), re-zero cnt; block 0 also folds the weights.
// ---------------------------------------------------------------------------
__global__ void k_dinv(int n,
                       const float* __restrict__ att,
                       const float* __restrict__ Wz, const float* __restrict__ bz,
                       const float* __restrict__ Lz, const float* __restrict__ lz,
                       const float* __restrict__ Wh, const float* __restrict__ bh,
                       const float* __restrict__ Lh, const float* __restrict__ lh,
                       const float* __restrict__ Wo, const float* __restrict__ bo) {
    if (blockIdx.x == 0 && threadIdx.x < 128) {
        int tid = threadIdx.x;
        int f = tid >> 5, c = tid & 31;
        float mz = 0.f, mh = 0.f;
        #pragma unroll 8
        for (int k = 0; k < 32; k++) {
            mz = fmaf(Wz[f * 32 + k], Lz[k * 32 + c], mz);
            mh = fmaf(Wh[f * 32 + k], Lh[k * 32 + c], mh);
        }
        g_c.Mz[f][c] = mz;
        g_c.Mh[f][c] = mh;
        if (f == 0) {
            float s1 = lz[c], s2 = lh[c];
            #pragma unroll 8
            for (int k = 0; k < 32; k++) {
                s1 = fmaf(bz[k], Lz[k * 32 + c], s1);
                s2 = fmaf(bh[k], Lh[k * 32 + c], s2);
            }
            g_c.cz[c] = s1;
            g_c.ch[c] = s2;
        }
        for (int i = tid; i < 32 * 12; i += 128) ((float*)g_c.Wo)[i] = Wo[i];
        if (tid < 12) g_c.bo[tid] = bo[tid];
        if (tid == 0) {
            float m = -1e30f;
            for (int t = 0; t < 12; t++) m = fmaxf(m, att[t]);
            float ex[12]; float s = 0.f;
            for (int t = 0; t < 12; t++) { ex[t] = expf(att[t] - m); s += ex[t]; }
            float inv = 0.5f / s;   // 0.5 from (1-sigmoid)*tanh identity folded here
            for (int t = 0; t < 12; t++) g_c.probs[t] = ex[t] * inv;
        }
    }
    int i = blockIdx.x * blockDim.x + threadIdx.x;
    if (i < n) {
        int d = g_cnt[i];
        g_cnt[i] = 0;                         // ready for next graph replay
        g_deg[i] = (d < CAP) ? d : CAP;
        g_dinv[i] = rsqrtf((float)d + 1.0f);  // +1 self loop
    }
}

// ---------------------------------------------------------------------------
// Kernel 3: warp-per-node fp16 gather, ONE 128B line per row.
// Lane = (slot = lane>>3 in 0..3, h = lane&7). One LDG.128 covers 4 edges
// (8 lanes/row, row = 1 aligned line -> 4 L1 wavefronts per LDG = 1/edge).
// 8 f32 accumulators, 2-step butterfly, MUFU.TANH GRU epilogue.
// ---------------------------------------------------------------------------
__device__ __forceinline__ float fast_tanh(float v) {
    float r;
    asm("tanh.approx.f32 %0, %1;" : "=f"(r) : "f"(v));
    return r;
}

__device__ __forceinline__ void fma8(float* acc, const uint4& c, float nr) {
    __half2 h0 = *reinterpret_cast<const __half2*>(&c.x);
    __half2 h1 = *reinterpret_cast<const __half2*>(&c.y);
    __half2 h2 = *reinterpret_cast<const __half2*>(&c.z);
    __half2 h3 = *reinterpret_cast<const __half2*>(&c.w);
    float2 f0 = __half22float2(h0);
    float2 f1 = __half22float2(h1);
    float2 f2 = __half22float2(h2);
    float2 f3 = __half22float2(h3);
    acc[0] = fmaf(f0.x, nr, acc[0]);
    acc[1] = fmaf(f0.y, nr, acc[1]);
    acc[2] = fmaf(f1.x, nr, acc[2]);
    acc[3] = fmaf(f1.y, nr, acc[3]);
    acc[4] = fmaf(f2.x, nr, acc[4]);
    acc[5] = fmaf(f2.y, nr, acc[5]);
    acc[6] = fmaf(f3.x, nr, acc[6]);
    acc[7] = fmaf(f3.y, nr, acc[7]);
}

__global__ void __launch_bounds__(256, 5) k_fused(float* __restrict__ out, int n) {
    __shared__ __align__(16) float sC[728];   // sizeof(Consts)/4
    __shared__ float shv[8][32];
    {
        const float* src = (const float*)&g_c;
        for (int i = threadIdx.x; i < 728; i += 256) sC[i] = src[i];
    }
    __syncthreads();
    const Consts* C = (const Consts*)sC;

    const unsigned FULL = 0xffffffffu;
    int warp = threadIdx.x >> 5, lane = threadIdx.x & 31;
    int node = blockIdx.x * 8 + warp;
    if (node >= n) return;

    int myslot = lane >> 3;   // 0..3: which of the 4 concurrent edges
    int h = lane & 7;         // 16B chunk within the row (6,7 = zero padding)
    int deg = g_deg[node];
    float dn = g_dinv[node];
    const int* adj = g_adj + (size_t)node * CAP;

    float acc[8];
    #pragma unroll
    for (int k = 0; k < 8; k++) acc[k] = 0.f;

    // self loop (norm = dn^2): slot 0 (lanes 0-7)
    if (myslot == 0) {
        uint4 c = g_xh[(size_t)node * 8 + h];
        fma8(acc, c, dn * dn);
    }

    int iters = (deg + 15) >> 4;   // 16 edges per group, 4 inner steps of 4
    // prefetch group 0's indices + dinv (lanes 0-15)
    int s = node; float dv = 0.f;
    if (lane < 16 && lane < deg) {
        s = adj[lane];
        dv = g_dinv[s];
    }

    for (int it = 0; it < iters; it++) {
        int   cur_s = s;
        float cur_dv = dv;
        int base = (it + 1) * 16;
        if (lane < 16) {
            int idx = base + lane;
            if (idx < deg) { s = adj[idx]; dv = g_dinv[s]; }
            else           { s = node;     dv = 0.f; }
        }
        #pragma unroll
        for (int k = 0; k < 4; k++) {
            int   row = __shfl_sync(FULL, cur_s, 4 * k + myslot);
            float nr  = __shfl_sync(FULL, cur_dv, 4 * k + myslot) * dn;  // 0 on pads
            uint4 c = g_xh[(size_t)row * 8 + h];
            fma8(acc, c, nr);
        }
    }

    // butterfly reduction over the 4 slots (lanes with equal h)
    #pragma unroll
    for (int d = 8; d < 32; d <<= 1) {
        #pragma unroll
        for (int k = 0; k < 8; k++)
            acc[k] += __shfl_xor_sync(FULL, acc[k], d);
    }
    // every lane now holds the 8 XA values of chunk h (h=0..5 real, 6,7 zero).

    // collapsed GRU: lane = output channel c
    float Mz0 = C->Mz[0][lane], Mz1 = C->Mz[1][lane], Mz2 = C->Mz[2][lane], Mz3 = C->Mz[3][lane];
    float Mh0 = C->Mh[0][lane], Mh1 = C->Mh[1][lane], Mh2 = C->Mh[2][lane], Mh3 = C->Mh[3][lane];
    float czc = C->cz[lane], chc = C->ch[lane];

    float H = 0.f;
    #pragma unroll
    for (int t = 0; t < 12; t++) {
        float xv[4];
        #pragma unroll
        for (int f = 0; f < 4; f++) {
            const int i = f * 12 + t;      // flat index into XA[48]
            const int hc = i >> 3;         // 8-value chunk 0..5
            const int j = i & 7;           // register within acc[8]
            xv[f] = __shfl_sync(FULL, acc[j], hc);
        }
        float pz = fmaf(xv[3], Mz3, fmaf(xv[2], Mz2, fmaf(xv[1], Mz1, fmaf(xv[0], Mz0, czc))));
        float ph = fmaf(xv[3], Mh3, fmaf(xv[2], Mh2, fmaf(xv[1], Mh1, fmaf(xv[0], Mh0, chc))));
        // (1 - sigmoid(pz)) * tanh(ph) = 0.5 * (1 - tanh(pz/2)) * tanh(ph);
        // the 0.5 is folded into C->probs.
        float tA = fast_tanh(0.5f * pz);
        float tB = fast_tanh(ph);
        float val = (1.0f - tA) * tB;
        H = fmaf(val, C->probs[t], H);
    }

    shv[warp][lane] = fmaxf(H, 0.f);
    __syncwarp();
    if (lane < 12) {
        float acc_o = C->bo[lane];
        #pragma unroll
        for (int c2 = 0; c2 < 32; c2++)
            acc_o = fmaf(shv[warp][c2], C->Wo[c2][lane], acc_o);
        out[(size_t)node * 12 + lane] = acc_o;
    }
}

// ---------------------------------------------------------------------------
extern "C" void kernel_launch(void* const* d_in, const int* in_sizes, int n_in,
                              void* d_out, int out_size) {
    const float* x   = (const float*)d_in[0];
    const int*   ei  = (const int*)  d_in[1];
    const float* att = (const float*)d_in[2];
    const float* Wz  = (const float*)d_in[3];
    const float* bz  = (const float*)d_in[4];
    const float* Lz  = (const float*)d_in[5];
    const float* lz  = (const float*)d_in[6];
    // d_in[7..10] = Wr, br, Lr, lr : provably unused (H0 == 0)
    const float* Wh  = (const float*)d_in[11];
    const float* bh  = (const float*)d_in[12];
    const float* Lh  = (const float*)d_in[13];
    const float* lh  = (const float*)d_in[14];
    const float* Wo  = (const float*)d_in[15];
    const float* bo  = (const float*)d_in[16];
    float* out = (float*)d_out;

    int n = in_sizes[0] / 48;   // [N, 4, 12]
    int e = in_sizes[1] / 2;    // [2, E]
    int nchunks = n * 8;        // one uint4 per chunk, 8 per node (padded)

    k_cvt <<<(nchunks + 255) / 256, 256>>>(x, nchunks);
    k_fill<<<(e + 1023) / 1024, 256>>>(ei, e);
    k_dinv<<<(n + 255) / 256, 256>>>(n, att, Wz, bz, Lz, lz, Wh, bh, Lh, lh, Wo, bo);
    k_fused<<<(n + 7) / 8, 256>>>(out, n);
}

// round 10
// speedup vs baseline: 1.3329x; 1.0082x over previous
#include <cuda_runtime.h>
#include <cuda_fp16.h>
#include <math.h>

// Problem constants (fixed dataset: N=50000, E=1.6M, avg in-degree 32)
#define MAXN 50048
#define CAP  128   // per-node adjacency capacity; Poisson(32) max over 50K nodes ~70

struct Consts {
    float Mz[4][32];   // Wz @ Lz[0:32,:]
    float Mh[4][32];   // Wh @ Lh[0:32,:]
    float cz[32];      // bz @ Lz[0:32,:] + lz
    float ch[32];      // bh @ Lh[0:32,:] + lh
    float probs[12];   // 0.5 * softmax(attention)  (0.5 folded from GRU identity)
    float Wo[32][12];
    float bo[12];
};

__device__ Consts g_c;
__device__ int   g_cnt[MAXN];               // zero-init at load; k_dinv re-zeroes
__device__ int   g_deg[MAXN];
__device__ float g_dinv[MAXN];
__device__ int   g_adj[(size_t)MAXN * CAP];
// One node row = 128 B = 8 x uint4: chunks 0-5 = 48 fp16 x-values,
// chunk 6.x = f32 dinv[node] (embedded so the gather needs NO dinv load),
// rest zero. 128B-aligned: each gathered row is exactly ONE L1 cache line.
__device__ __align__(128) uint4 g_xh[(size_t)MAXN * 8];

// ---------------------------------------------------------------------------
// Kernel 0 (runs AFTER k_dinv): pack fp16 row + embedded f32 dinv.
// ---------------------------------------------------------------------------
__global__ void k_cvt(const float* __restrict__ x, int nchunks) {
    int i = blockIdx.x * blockDim.x + threadIdx.x;   // one uint4 out
    if (i >= nchunks) return;
    int node = i >> 3, h = i & 7;
    uint4 o = make_uint4(0u, 0u, 0u, 0u);
    if (h < 6) {
        const float4* src = (const float4*)(x + (size_t)node * 48 + h * 8);
        float4 a = src[0];
        float4 b = src[1];
        __half2 h0 = __floats2half2_rn(a.x, a.y);
        __half2 h1 = __floats2half2_rn(a.z, a.w);
        __half2 h2 = __floats2half2_rn(b.x, b.y);
        __half2 h3 = __floats2half2_rn(b.z, b.w);
        o.x = *reinterpret_cast<unsigned*>(&h0);
        o.y = *reinterpret_cast<unsigned*>(&h1);
        o.z = *reinterpret_cast<unsigned*>(&h2);
        o.w = *reinterpret_cast<unsigned*>(&h3);
    } else if (h == 6) {
        o.x = __float_as_uint(g_dinv[node]);   // embedded norm factor
    }
    g_xh[i] = o;
}

// ---------------------------------------------------------------------------
// Kernel 1: single-pass bucketed adjacency build (best cfg: 4 edges/thread).
// ---------------------------------------------------------------------------
__global__ void k_fill(const int* __restrict__ ei, int e) {
    int t = blockIdx.x * blockDim.x + threadIdx.x;
    int i4 = t * 4;
    if (i4 >= e) return;
    if ((e & 3) == 0) {   // dataset path: e divisible by 4
        int4 r = *reinterpret_cast<const int4*>(ei + i4);       // sources
        int4 c = *reinterpret_cast<const int4*>(ei + e + i4);   // targets
        int p0 = atomicAdd(&g_cnt[c.x], 1);
        int p1 = atomicAdd(&g_cnt[c.y], 1);
        int p2 = atomicAdd(&g_cnt[c.z], 1);
        int p3 = atomicAdd(&g_cnt[c.w], 1);
        if (p0 < CAP) g_adj[(size_t)c.x * CAP + p0] = r.x;
        if (p1 < CAP) g_adj[(size_t)c.y * CAP + p1] = r.y;
        if (p2 < CAP) g_adj[(size_t)c.z * CAP + p2] = r.z;
        if (p3 < CAP) g_adj[(size_t)c.w * CAP + p3] = r.w;
    } else {
        int end = min(i4 + 4, e);
        for (int i = i4; i < end; i++) {
            int rr = ei[i], cc = ei[e + i];
            int p = atomicAdd(&g_cnt[cc], 1);
            if (p < CAP) g_adj[(size_t)cc * CAP + p] = rr;
        }
    }
}

// ---------------------------------------------------------------------------
// Kernel 2: cnt -> (deg, dinv), re-zero cnt; block 0 also folds the weights.
// ---------------------------------------------------------------------------
__global__ void k_dinv(int n,
                       const float* __restrict__ att,
                       const float* __restrict__ Wz, const float* __restrict__ bz,
                       const float* __restrict__ Lz, const float* __restrict__ lz,
                       const float* __restrict__ Wh, const float* __restrict__ bh,
                       const float* __restrict__ Lh, const float* __restrict__ lh,
                       const float* __restrict__ Wo, const float* __restrict__ bo) {
    if (blockIdx.x == 0 && threadIdx.x < 128) {
        int tid = threadIdx.x;
        int f = tid >> 5, c = tid & 31;
        float mz = 0.f, mh = 0.f;
        #pragma unroll 8
        for (int k = 0; k < 32; k++) {
            mz = fmaf(Wz[f * 32 + k], Lz[k * 32 + c], mz);
            mh = fmaf(Wh[f * 32 + k], Lh[k * 32 + c], mh);
        }
        g_c.Mz[f][c] = mz;
        g_c.Mh[f][c] = mh;
        if (f == 0) {
            float s1 = lz[c], s2 = lh[c];
            #pragma unroll 8
            for (int k = 0; k < 32; k++) {
                s1 = fmaf(bz[k], Lz[k * 32 + c], s1);
                s2 = fmaf(bh[k], Lh[k * 32 + c], s2);
            }
            g_c.cz[c] = s1;
            g_c.ch[c] = s2;
        }
        for (int i = tid; i < 32 * 12; i += 128) ((float*)g_c.Wo)[i] = Wo[i];
        if (tid < 12) g_c.bo[tid] = bo[tid];
        if (tid == 0) {
            float m = -1e30f;
            for (int t = 0; t < 12; t++) m = fmaxf(m, att[t]);
            float ex[12]; float s = 0.f;
            for (int t = 0; t < 12; t++) { ex[t] = expf(att[t] - m); s += ex[t]; }
            float inv = 0.5f / s;   // 0.5 from (1-sigmoid)*tanh identity folded here
            for (int t = 0; t < 12; t++) g_c.probs[t] = ex[t] * inv;
        }
    }
    int i = blockIdx.x * blockDim.x + threadIdx.x;
    if (i < n) {
        int d = g_cnt[i];
        g_cnt[i] = 0;                         // ready for next graph replay
        g_deg[i] = (d < CAP) ? d : CAP;
        g_dinv[i] = rsqrtf((float)d + 1.0f);  // +1 self loop
    }
}

// ---------------------------------------------------------------------------
// Kernel 3: warp-per-node gather. Lane = (slot = lane>>3, h = lane&7).
// One LDG.128 covers 4 edges; row = 1 aligned 128B line; the row CARRIES its
// own dinv (chunk 6) so there is no scattered dinv load at all.
// Pad edges are sign-bit flagged in the adjacency value -> nr = 0.
// ---------------------------------------------------------------------------
__device__ __forceinline__ float fast_tanh(float v) {
    float r;
    asm("tanh.approx.f32 %0, %1;" : "=f"(r) : "f"(v));
    return r;
}

__device__ __forceinline__ void fma8(float* acc, const uint4& c, float nr) {
    __half2 h0 = *reinterpret_cast<const __half2*>(&c.x);
    __half2 h1 = *reinterpret_cast<const __half2*>(&c.y);
    __half2 h2 = *reinterpret_cast<const __half2*>(&c.z);
    __half2 h3 = *reinterpret_cast<const __half2*>(&c.w);
    float2 f0 = __half22float2(h0);
    float2 f1 = __half22float2(h1);
    float2 f2 = __half22float2(h2);
    float2 f3 = __half22float2(h3);
    acc[0] = fmaf(f0.x, nr, acc[0]);
    acc[1] = fmaf(f0.y, nr, acc[1]);
    acc[2] = fmaf(f1.x, nr, acc[2]);
    acc[3] = fmaf(f1.y, nr, acc[3]);
    acc[4] = fmaf(f2.x, nr, acc[4]);
    acc[5] = fmaf(f2.y, nr, acc[5]);
    acc[6] = fmaf(f3.x, nr, acc[6]);
    acc[7] = fmaf(f3.y, nr, acc[7]);
}

__global__ void __launch_bounds__(256, 5) k_fused(float* __restrict__ out, int n) {
    __shared__ __align__(16) float sC[728];   // sizeof(Consts)/4
    __shared__ float shv[8][32];
    {
        const float* src = (const float*)&g_c;
        for (int i = threadIdx.x; i < 728; i += 256) sC[i] = src[i];
    }
    __syncthreads();
    const Consts* C = (const Consts*)sC;

    const unsigned FULL = 0xffffffffu;
    int warp = threadIdx.x >> 5, lane = threadIdx.x & 31;
    int node = blockIdx.x * 8 + warp;
    if (node >= n) return;

    int myslot = lane >> 3;   // 0..3: which of the 4 concurrent edges
    int h = lane & 7;         // 16B chunk within the row (6 = dinv, 7 = pad)
    int dvlane = (myslot << 3) + 6;   // lane holding my slot's dinv after LDG
    int deg = g_deg[node];
    float dn = g_dinv[node];
    const int* adj = g_adj + (size_t)node * CAP;

    float acc[8];
    #pragma unroll
    for (int k = 0; k < 8; k++) acc[k] = 0.f;

    // self loop (norm = dn^2): slot 0 (lanes 0-7)
    if (myslot == 0) {
        uint4 c = g_xh[(size_t)node * 8 + h];
        fma8(acc, c, dn * dn);
    }

    int iters = (deg + 15) >> 4;   // 16 edges per group, 4 inner steps of 4
    // prefetch group 0's indices (lanes 0-15); sign bit marks pad slots
    int s = node | 0x80000000;
    if (lane < 16 && lane < deg) s = adj[lane];

    for (int it = 0; it < iters; it++) {
        int cur_s = s;
        int base = (it + 1) * 16;
        if (lane < 16) {
            int idx = base + lane;
            s = (idx < deg) ? adj[idx] : (node | 0x80000000);
        }
        #pragma unroll
        for (int k = 0; k < 4; k++) {
            int rowEnc = __shfl_sync(FULL, cur_s, 4 * k + myslot);
            int row = rowEnc & 0x7fffffff;
            uint4 c = g_xh[(size_t)row * 8 + h];
            float dvs = __shfl_sync(FULL, __uint_as_float(c.x), dvlane);
            float nr = (rowEnc < 0) ? 0.f : dvs * dn;
            fma8(acc, c, nr);
        }
    }

    // butterfly reduction over the 4 slots (lanes with equal h)
    #pragma unroll
    for (int d = 8; d < 32; d <<= 1) {
        #pragma unroll
        for (int k = 0; k < 8; k++)
            acc[k] += __shfl_xor_sync(FULL, acc[k], d);
    }
    // lanes h=0..5 hold the 8 XA values of chunk h (6,7 = garbage, never read).

    // collapsed GRU: lane = output channel c
    float Mz0 = C->Mz[0][lane], Mz1 = C->Mz[1][lane], Mz2 = C->Mz[2][lane], Mz3 = C->Mz[3][lane];
    float Mh0 = C->Mh[0][lane], Mh1 = C->Mh[1][lane], Mh2 = C->Mh[2][lane], Mh3 = C->Mh[3][lane];
    float czc = C->cz[lane], chc = C->ch[lane];

    float H = 0.f;
    #pragma unroll
    for (int t = 0; t < 12; t++) {
        float xv[4];
        #pragma unroll
        for (int f = 0; f < 4; f++) {
            const int i = f * 12 + t;      // flat index into XA[48]
            const int hc = i >> 3;         // 8-value chunk 0..5
            const int j = i & 7;           // register within acc[8]
            xv[f] = __shfl_sync(FULL, acc[j], hc);
        }
        float pz = fmaf(xv[3], Mz3, fmaf(xv[2], Mz2, fmaf(xv[1], Mz1, fmaf(xv[0], Mz0, czc))));
        float ph = fmaf(xv[3], Mh3, fmaf(xv[2], Mh2, fmaf(xv[1], Mh1, fmaf(xv[0], Mh0, chc))));
        // (1 - sigmoid(pz)) * tanh(ph) = 0.5 * (1 - tanh(pz/2)) * tanh(ph);
        // the 0.5 is folded into C->probs.
        float tA = fast_tanh(0.5f * pz);
        float tB = fast_tanh(ph);
        float val = (1.0f - tA) * tB;
        H = fmaf(val, C->probs[t], H);
    }

    shv[warp][lane] = fmaxf(H, 0.f);
    __syncwarp();
    if (lane < 12) {
        float acc_o = C->bo[lane];
        #pragma unroll
        for (int c2 = 0; c2 < 32; c2++)
            acc_o = fmaf(shv[warp][c2], C->Wo[c2][lane], acc_o);
        out[(size_t)node * 12 + lane] = acc_o;
    }
}

// ---------------------------------------------------------------------------
extern "C" void kernel_launch(void* const* d_in, const int* in_sizes, int n_in,
                              void* d_out, int out_size) {
    const float* x   = (const float*)d_in[0];
    const int*   ei  = (const int*)  d_in[1];
    const float* att = (const float*)d_in[2];
    const float* Wz  = (const float*)d_in[3];
    const float* bz  = (const float*)d_in[4];
    const float* Lz  = (const float*)d_in[5];
    const float* lz  = (const float*)d_in[6];
    // d_in[7..10] = Wr, br, Lr, lr : provably unused (H0 == 0)
    const float* Wh  = (const float*)d_in[11];
    const float* bh  = (const float*)d_in[12];
    const float* Lh  = (const float*)d_in[13];
    const float* lh  = (const float*)d_in[14];
    const float* Wo  = (const float*)d_in[15];
    const float* bo  = (const float*)d_in[16];
    float* out = (float*)d_out;

    int n = in_sizes[0] / 48;   // [N, 4, 12]
    int e = in_sizes[1] / 2;    // [2, E]
    int nchunks = n * 8;        // one uint4 per chunk, 8 per node (padded)

    k_fill<<<(e + 1023) / 1024, 256>>>(ei, e);
    k_dinv<<<(n + 255) / 256, 256>>>(n, att, Wz, bz, Lz, lz, Wh, bh, Lh, lh, Wo, bo);
    k_cvt <<<(nchunks + 255) / 256, 256>>>(x, nchunks);   // needs g_dinv -> after k_dinv
    k_fused<<<(n + 7) / 8, 256>>>(out, n);
}

// round 11
// speedup vs baseline: 1.3818x; 1.0366x over previous
#include <cuda_runtime.h>
#include <cuda_fp16.h>
#include <math.h>

// Problem constants (fixed dataset: N=50000, E=1.6M, avg in-degree 32)
#define MAXN 50048
#define CAP  128           // per-node adjacency capacity; Poisson(32) max << 128
#define ZROW (MAXN - 1)    // guaranteed all-zero row (never written; BSS zero-init)

struct Consts {
    float Mz[4][32];   // Wz @ Lz[0:32,:]
    float Mh[4][32];   // Wh @ Lh[0:32,:]
    float cz[32];      // bz @ Lz[0:32,:] + lz
    float ch[32];      // bh @ Lh[0:32,:] + lh
    float probs[12];   // 0.5 * softmax(attention)  (0.5 folded from GRU identity)
    float Wo[32][12];
    float bo[12];
};

__device__ Consts g_c;
__device__ int   g_cnt[MAXN];               // zero-init at load; k_cvt re-zeroes
__device__ int   g_deg[MAXN];
__device__ float g_dinv[MAXN];
__device__ int   g_adj[(size_t)MAXN * CAP];
// One node row = 128 B = 8 x uint4: chunks 0-5 = 48 fp16 values of
// x[node]*dinv[node] (PRE-SCALED: per-edge norm reduces to the loop-constant
// dn), chunks 6-7 zero. 128B-aligned: each gathered row = ONE L1 cache line.
// Rows >= n are never written -> stay zero -> pad edges point at ZROW.
__device__ __align__(128) uint4 g_xh[(size_t)MAXN * 8];

// ---------------------------------------------------------------------------
// Kernel 1: single-pass bucketed adjacency build (best cfg: 4 edges/thread).
// ---------------------------------------------------------------------------
__global__ void k_fill(const int* __restrict__ ei, int e) {
    int t = blockIdx.x * blockDim.x + threadIdx.x;
    int i4 = t * 4;
    if (i4 >= e) return;
    if ((e & 3) == 0) {   // dataset path: e divisible by 4
        int4 r = *reinterpret_cast<const int4*>(ei + i4);       // sources
        int4 c = *reinterpret_cast<const int4*>(ei + e + i4);   // targets
        int p0 = atomicAdd(&g_cnt[c.x], 1);
        int p1 = atomicAdd(&g_cnt[c.y], 1);
        int p2 = atomicAdd(&g_cnt[c.z], 1);
        int p3 = atomicAdd(&g_cnt[c.w], 1);
        if (p0 < CAP) g_adj[(size_t)c.x * CAP + p0] = r.x;
        if (p1 < CAP) g_adj[(size_t)c.y * CAP + p1] = r.y;
        if (p2 < CAP) g_adj[(size_t)c.z * CAP + p2] = r.z;
        if (p3 < CAP) g_adj[(size_t)c.w * CAP + p3] = r.w;
    } else {
        int end = min(i4 + 4, e);
        for (int i = i4; i < end; i++) {
            int rr = ei[i], cc = ei[e + i];
            int p = atomicAdd(&g_cnt[cc], 1);
            if (p < CAP) g_adj[(size_t)cc * CAP + p] = rr;
        }
    }
}

// ---------------------------------------------------------------------------
// Kernel 2: weight fold only (1 block, 128 threads).
// ---------------------------------------------------------------------------
__global__ void k_prep(const float* __restrict__ att,
                       const float* __restrict__ Wz, const float* __restrict__ bz,
                       const float* __restrict__ Lz, const float* __restrict__ lz,
                       const float* __restrict__ Wh, const float* __restrict__ bh,
                       const float* __restrict__ Lh, const float* __restrict__ lh,
                       const float* __restrict__ Wo, const float* __restrict__ bo) {
    int tid = threadIdx.x;
    int f = tid >> 5, c = tid & 31;
    float mz = 0.f, mh = 0.f;
    #pragma unroll 8
    for (int k = 0; k < 32; k++) {
        mz = fmaf(Wz[f * 32 + k], Lz[k * 32 + c], mz);
        mh = fmaf(Wh[f * 32 + k], Lh[k * 32 + c], mh);
    }
    g_c.Mz[f][c] = mz;
    g_c.Mh[f][c] = mh;
    if (f == 0) {
        float s1 = lz[c], s2 = lh[c];
        #pragma unroll 8
        for (int k = 0; k < 32; k++) {
            s1 = fmaf(bz[k], Lz[k * 32 + c], s1);
            s2 = fmaf(bh[k], Lh[k * 32 + c], s2);
        }
        g_c.cz[c] = s1;
        g_c.ch[c] = s2;
    }
    for (int i = tid; i < 32 * 12; i += 128) ((float*)g_c.Wo)[i] = Wo[i];
    if (tid < 12) g_c.bo[tid] = bo[tid];
    if (tid == 0) {
        float m = -1e30f;
        for (int t = 0; t < 12; t++) m = fmaxf(m, att[t]);
        float ex[12]; float s = 0.f;
        for (int t = 0; t < 12; t++) { ex[t] = expf(att[t] - m); s += ex[t]; }
        float inv = 0.5f / s;   // 0.5 from (1-sigmoid)*tanh identity folded here
        for (int t = 0; t < 12; t++) g_c.probs[t] = ex[t] * inv;
    }
}

// ---------------------------------------------------------------------------
// Kernel 3 (after k_fill): per-node pass fused:
//   dinv = rsqrt(cnt+1); pack fp16(x * dinv) row; write deg/dinv; re-zero cnt.
// A node's 8 chunk-threads are consecutive (8-aligned) -> one warp; __syncwarp
// orders the g_cnt reads before the h==7 lane re-zeroes it.
// ---------------------------------------------------------------------------
__global__ void k_cvt(const float* __restrict__ x, int nchunks) {
    int i = blockIdx.x * blockDim.x + threadIdx.x;   // one uint4 out
    int node = i >> 3, h = i & 7;
    int d = 0;
    if (i < nchunks) d = g_cnt[node];
    __syncwarp();
    if (i >= nchunks) return;
    float dv = rsqrtf((float)d + 1.0f);   // +1 self loop
    uint4 o = make_uint4(0u, 0u, 0u, 0u);
    if (h < 6) {
        const float4* src = (const float4*)(x + (size_t)node * 48 + h * 8);
        float4 a = src[0];
        float4 b = src[1];
        __half2 h0 = __floats2half2_rn(a.x * dv, a.y * dv);
        __half2 h1 = __floats2half2_rn(a.z * dv, a.w * dv);
        __half2 h2 = __floats2half2_rn(b.x * dv, b.y * dv);
        __half2 h3 = __floats2half2_rn(b.z * dv, b.w * dv);
        o.x = *reinterpret_cast<unsigned*>(&h0);
        o.y = *reinterpret_cast<unsigned*>(&h1);
        o.z = *reinterpret_cast<unsigned*>(&h2);
        o.w = *reinterpret_cast<unsigned*>(&h3);
    } else if (h == 7) {
        g_cnt[node] = 0;                       // ready for next replay
        g_deg[node] = (d < CAP) ? d : CAP;
        g_dinv[node] = dv;
    }
    g_xh[i] = o;
}

// ---------------------------------------------------------------------------
// Kernel 4: warp-per-node gather. Lane = (slot = lane>>3, h = lane&7).
// One LDG.128 covers 4 edges; rows are PRE-SCALED so the mainloop is pure
// cvt+add (no per-edge norm, no select, no dinv shfl). Pads hit the zero row.
// XA = dn * (sum of pre-scaled rows) applied once after the butterfly.
// ---------------------------------------------------------------------------
__device__ __forceinline__ float fast_tanh(float v) {
    float r;
    asm("tanh.approx.f32 %0, %1;" : "=f"(r) : "f"(v));
    return r;
}

__device__ __forceinline__ void add8(float* acc, const uint4& c) {
    __half2 h0 = *reinterpret_cast<const __half2*>(&c.x);
    __half2 h1 = *reinterpret_cast<const __half2*>(&c.y);
    __half2 h2 = *reinterpret_cast<const __half2*>(&c.z);
    __half2 h3 = *reinterpret_cast<const __half2*>(&c.w);
    float2 f0 = __half22float2(h0);
    float2 f1 = __half22float2(h1);
    float2 f2 = __half22float2(h2);
    float2 f3 = __half22float2(h3);
    acc[0] += f0.x; acc[1] += f0.y;
    acc[2] += f1.x; acc[3] += f1.y;
    acc[4] += f2.x; acc[5] += f2.y;
    acc[6] += f3.x; acc[7] += f3.y;
}

__global__ void __launch_bounds__(256, 6) k_fused(float* __restrict__ out, int n) {
    __shared__ __align__(16) float sC[728];   // sizeof(Consts)/4
    __shared__ float shv[8][32];
    {
        const float* src = (const float*)&g_c;
        for (int i = threadIdx.x; i < 728; i += 256) sC[i] = src[i];
    }
    __syncthreads();
    const Consts* C = (const Consts*)sC;

    const unsigned FULL = 0xffffffffu;
    int warp = threadIdx.x >> 5, lane = threadIdx.x & 31;
    int node = blockIdx.x * 8 + warp;
    if (node >= n) return;

    int myslot = lane >> 3;   // 0..3: which of the 4 concurrent edges
    int h = lane & 7;         // 16B chunk within the row
    int deg = g_deg[node];
    float dn = g_dinv[node];
    const int* adj = g_adj + (size_t)node * CAP;

    float acc[8];
    #pragma unroll
    for (int k = 0; k < 8; k++) acc[k] = 0.f;

    // self loop: own pre-scaled row (x*dn); after the final *dn -> dn^2 * x.
    if (myslot == 0) add8(acc, g_xh[(size_t)node * 8 + h]);

    int iters = (deg + 15) >> 4;   // 16 edges per group, 4 inner steps of 4
    // prefetch group 0's indices (lanes 0-15); pads -> zero row
    int s = ZROW;
    if (lane < 16 && lane < deg) s = adj[lane];

    for (int it = 0; it < iters; it++) {
        int cur_s = s;
        int base = (it + 1) * 16;
        if (lane < 16) {
            int idx = base + lane;
            s = (idx < deg) ? adj[idx] : ZROW;
        }
        #pragma unroll
        for (int k = 0; k < 4; k++) {
            int row = __shfl_sync(FULL, cur_s, 4 * k + myslot);
            add8(acc, g_xh[(size_t)row * 8 + h]);
        }
    }

    // butterfly reduction over the 4 slots (lanes with equal h), then norm.
    #pragma unroll
    for (int d = 8; d < 32; d <<= 1) {
        #pragma unroll
        for (int k = 0; k < 8; k++)
            acc[k] += __shfl_xor_sync(FULL, acc[k], d);
    }
    #pragma unroll
    for (int k = 0; k < 8; k++) acc[k] *= dn;
    // lanes h=0..5 hold the 8 XA values of chunk h (6,7 = zero, never read).

    // collapsed GRU: lane = output channel c
    float Mz0 = C->Mz[0][lane], Mz1 = C->Mz[1][lane], Mz2 = C->Mz[2][lane], Mz3 = C->Mz[3][lane];
    float Mh0 = C->Mh[0][lane], Mh1 = C->Mh[1][lane], Mh2 = C->Mh[2][lane], Mh3 = C->Mh[3][lane];
    float czc = C->cz[lane], chc = C->ch[lane];

    float H = 0.f;
    #pragma unroll
    for (int t = 0; t < 12; t++) {
        float xv[4];
        #pragma unroll
        for (int f = 0; f < 4; f++) {
            const int i = f * 12 + t;      // flat index into XA[48]
            const int hc = i >> 3;         // 8-value chunk 0..5
            const int j = i & 7;           // register within acc[8]
            xv[f] = __shfl_sync(FULL, acc[j], hc);
        }
        float pz = fmaf(xv[3], Mz3, fmaf(xv[2], Mz2, fmaf(xv[1], Mz1, fmaf(xv[0], Mz0, czc))));
        float ph = fmaf(xv[3], Mh3, fmaf(xv[2], Mh2, fmaf(xv[1], Mh1, fmaf(xv[0], Mh0, chc))));
        // (1 - sigmoid(pz)) * tanh(ph) = 0.5 * (1 - tanh(pz/2)) * tanh(ph);
        // the 0.5 is folded into C->probs.
        float tA = fast_tanh(0.5f * pz);
        float tB = fast_tanh(ph);
        float val = (1.0f - tA) * tB;
        H = fmaf(val, C->probs[t], H);
    }

    shv[warp][lane] = fmaxf(H, 0.f);
    __syncwarp();
    if (lane < 12) {
        float acc_o = C->bo[lane];
        #pragma unroll
        for (int c2 = 0; c2 < 32; c2++)
            acc_o = fmaf(shv[warp][c2], C->Wo[c2][lane], acc_o);
        out[(size_t)node * 12 + lane] = acc_o;
    }
}

// ---------------------------------------------------------------------------
extern "C" void kernel_launch(void* const* d_in, const int* in_sizes, int n_in,
                              void* d_out, int out_size) {
    const float* x   = (const float*)d_in[0];
    const int*   ei  = (const int*)  d_in[1];
    const float* att = (const float*)d_in[2];
    const float* Wz  = (const float*)d_in[3];
    const float* bz  = (const float*)d_in[4];
    const float* Lz  = (const float*)d_in[5];
    const float* lz  = (const float*)d_in[6];
    // d_in[7..10] = Wr, br, Lr, lr : provably unused (H0 == 0)
    const float* Wh  = (const float*)d_in[11];
    const float* bh  = (const float*)d_in[12];
    const float* Lh  = (const float*)d_in[13];
    const float* lh  = (const float*)d_in[14];
    const float* Wo  = (const float*)d_in[15];
    const float* bo  = (const float*)d_in[16];
    float* out = (float*)d_out;

    int n = in_sizes[0] / 48;   // [N, 4, 12]
    int e = in_sizes[1] / 2;    // [2, E]
    int nchunks = n * 8;        // one uint4 per chunk, 8 per node (padded)

    k_fill<<<(e + 1023) / 1024, 256>>>(ei, e);
    k_prep<<<1, 128>>>(att, Wz, bz, Lz, lz, Wh, bh, Lh, lh, Wo, bo);
    k_cvt <<<(nchunks + 255) / 256, 256>>>(x, nchunks);   // needs g_cnt -> after k_fill
    k_fused<<<(n + 7) / 8, 256>>>(out, n);
}